// round 2
// baseline (speedup 1.0000x reference)
#include <cuda_runtime.h>

#define EPSV  1e-5f
#define SLOPEV 0.01f

// ---------------- device scratch (no allocation allowed) ----------------
__device__ float g_wT[512 * 128];          // conv_w transposed: [c][d]
__device__ float g_spa[16 * 4096];         // sigmoid(spatial SE) per (b, pixel)
__device__ float g_partE[16 * 32 * 2048];  // per-(b,tile) partial E (K*D)
__device__ float g_partA[16 * 32 * 16];    // per-(b,tile) partial sum_n A
__device__ float g_chn[16 * 512];          // channel SE per (b, c)

__device__ __forceinline__ float lrelu(float v) { return v >= 0.f ? v : SLOPEV * v; }
__device__ __forceinline__ float sigm(float v) { return 1.f / (1.f + expf(-v)); }

// ---------------- K0: transpose conv_w (D=128, C=512) -> wT[c][d] ----------------
__global__ void k_transpose_w(const float* __restrict__ w) {
    int i = blockIdx.x * 256 + threadIdx.x;   // i = d*512 + c, 65536 total
    int d = i >> 9, c = i & 511;
    g_wT[c * 128 + d] = w[i];
}

// ---------------- K1: fused ABN->ABN1->conv->ABN2->encoding partials + spa ----------------
// grid = 16*32 blocks (b, tile of 128 pixels); 256 threads.
// smem layout (floats), total 23072:
//   [0,16512)        X_s  (128 pixels x 129 stride)  -- phase B
//     overlay (phase A):
//       [0,512) s0 | [512,1024) b0 | [1024,1536) s1 | [1536,2048) b1 | [2048,2560) spw
//       [2560,2560+2112) y_s (16 x 132) | [4672,4672+2112) w_s (16 x 132)
//   [16512,18688)    A_s (128 x 17)
//   [18688,20736)    cw_s (16 x 128)
//   [20736,20752)    c2_s  | [20752,20768) sc_s
//   [20768,20896)    s2_s  | [20896,21024) t2_s
//   [21024,23072)    spa partials (16 x 128)
__global__ void __launch_bounds__(256) k_main(
    const float* __restrict__ x,
    const float* __restrict__ pre_g, const float* __restrict__ pre_b,
    const float* __restrict__ pre_m, const float* __restrict__ pre_v,
    const float* __restrict__ a1_g, const float* __restrict__ a1_b,
    const float* __restrict__ a1_m, const float* __restrict__ a1_v,
    const float* __restrict__ conv_b,
    const float* __restrict__ a2_g, const float* __restrict__ a2_b,
    const float* __restrict__ a2_m, const float* __restrict__ a2_v,
    const float* __restrict__ cw, const float* __restrict__ scale,
    const float* __restrict__ spa_w)
{
    extern __shared__ float sm[];
    float* X_s  = sm;             // stride 129
    float* A_s  = sm + 16512;     // stride 17
    float* cw_s = sm + 18688;
    float* c2_s = sm + 20736;
    float* sc_s = sm + 20752;
    float* s2_s = sm + 20768;
    float* t2_s = sm + 20896;
    float* spp  = sm + 21024;
    // phase-A overlay
    float* s0_s = sm;
    float* b0_s = sm + 512;
    float* s1_s = sm + 1024;
    float* b1_s = sm + 1536;
    float* spw_s= sm + 2048;
    float* y_s  = sm + 2560;      // stride 132
    float* w_s  = sm + 4672;      // stride 132

    const int t = threadIdx.x;
    const int b = blockIdx.x >> 5;
    const int tile = blockIdx.x & 31;
    const int n0 = tile * 128;

    // ---- load constants ----
    for (int i = t; i < 512; i += 256) {
        float s0 = pre_g[i] * rsqrtf(pre_v[i] + EPSV);
        s0_s[i] = s0; b0_s[i] = pre_b[i] - pre_m[i] * s0;
        float s1 = a1_g[i] * rsqrtf(a1_v[i] + EPSV);
        s1_s[i] = s1; b1_s[i] = a1_b[i] - a1_m[i] * s1;
        spw_s[i] = spa_w[i];
    }
    if (t < 128) {
        float s2 = a2_g[t] * rsqrtf(a2_v[t] + EPSV);
        s2_s[t] = s2;
        t2_s[t] = (a2_b[t] - a2_m[t] * s2) + conv_b[t] * s2;
    }
    for (int i = t; i < 2048; i += 256) cw_s[i] = cw[i];
    if (t < 16) {
        float c2 = 0.f;
        for (int d = 0; d < 128; d++) { float v = cw[t * 128 + d]; c2 += v * v; }
        c2_s[t] = c2; sc_s[t] = scale[t];
    }
    __syncthreads();

    // ---- GEMM: z[128 d][128 n] = wT^T @ y ----
    const int tx = t & 15;   // pixel group (8 pixels)
    const int ty = t >> 4;   // d group (8 d's) AND channel-in-chunk for loads
    float acc[8][8];
    #pragma unroll
    for (int i = 0; i < 8; i++)
        #pragma unroll
        for (int j = 0; j < 8; j++) acc[i][j] = 0.f;
    float spa_acc[8] = {0,0,0,0,0,0,0,0};

    const float* xbase = x + ((size_t)b * 512) * 4096 + n0 + tx * 8;

    for (int kc = 0; kc < 512; kc += 16) {
        int c = kc + ty;
        const float4* xp = (const float4*)(xbase + (size_t)c * 4096);
        float4 v0 = xp[0], v1 = xp[1];
        float xv[8] = {v0.x, v0.y, v0.z, v0.w, v1.x, v1.y, v1.z, v1.w};
        float s0 = s0_s[c], b0 = b0_s[c], s1 = s1_s[c], b1 = b1_s[c], sw = spw_s[c];
        float* yrow = y_s + ty * 132 + tx * 8;
        #pragma unroll
        for (int j = 0; j < 8; j++) {
            float p = lrelu(xv[j] * s0 + b0);
            spa_acc[j] += sw * p;
            yrow[j] = lrelu(p * s1 + b1);
        }
        // w chunk: rows = channel-in-chunk, cols = d
        const float4* wp = (const float4*)(g_wT + (size_t)c * 128 + tx * 8);
        float4 w0 = wp[0], w1 = wp[1];
        float* wrow = w_s + ty * 132 + tx * 8;
        wrow[0]=w0.x; wrow[1]=w0.y; wrow[2]=w0.z; wrow[3]=w0.w;
        wrow[4]=w1.x; wrow[5]=w1.y; wrow[6]=w1.z; wrow[7]=w1.w;
        __syncthreads();
        #pragma unroll
        for (int k = 0; k < 16; k++) {
            float wf[8], yf[8];
            #pragma unroll
            for (int i = 0; i < 8; i++) wf[i] = w_s[k * 132 + ty * 8 + i];
            #pragma unroll
            for (int j = 0; j < 8; j++) yf[j] = y_s[k * 132 + tx * 8 + j];
            #pragma unroll
            for (int i = 0; i < 8; i++)
                #pragma unroll
                for (int j = 0; j < 8; j++) acc[i][j] += wf[i] * yf[j];
        }
        __syncthreads();
    }

    // ---- ABN2 -> X_s, spa partials ----
    #pragma unroll
    for (int i = 0; i < 8; i++) {
        int d = ty * 8 + i;
        float s2 = s2_s[d], t2 = t2_s[d];
        #pragma unroll
        for (int j = 0; j < 8; j++) {
            int n = tx * 8 + j;
            X_s[n * 129 + d] = lrelu(acc[i][j] * s2 + t2);
        }
    }
    #pragma unroll
    for (int j = 0; j < 8; j++) spp[ty * 128 + tx * 8 + j] = spa_acc[j];
    __syncthreads();

    if (t < 128) {
        float s = 0.f;
        #pragma unroll
        for (int r = 0; r < 16; r++) s += spp[r * 128 + t];
        g_spa[b * 4096 + n0 + t] = sigm(s);
    }

    // ---- per-pixel scaled-L2 softmax -> A_s ----
    if (t < 128) {
        const float* Xr = X_s + t * 129;
        float x2 = 0.f;
        for (int d = 0; d < 128; d++) { float xv = Xr[d]; x2 += xv * xv; }
        float e[16]; float mx = -1e30f;
        #pragma unroll
        for (int k = 0; k < 16; k++) {
            float dot = 0.f;
            const float* cwr = cw_s + k * 128;
            for (int d = 0; d < 128; d++) dot += Xr[d] * cwr[d];
            float sl = sc_s[k] * (x2 - 2.f * dot + c2_s[k]);
            e[k] = sl; mx = fmaxf(mx, sl);
        }
        float sum = 0.f;
        #pragma unroll
        for (int k = 0; k < 16; k++) { e[k] = expf(e[k] - mx); sum += e[k]; }
        float inv = 1.f / sum;
        #pragma unroll
        for (int k = 0; k < 16; k++) A_s[t * 17 + k] = e[k] * inv;
    }
    __syncthreads();

    // ---- partial E (K x D) and asum ----
    {
        int kk = t >> 4;        // 0..15
        int dg = t & 15;        // 0..15
        int d0 = dg * 8;
        float ev[8] = {0,0,0,0,0,0,0,0};
        float as = 0.f;
        for (int n = 0; n < 128; n++) {
            float a = A_s[n * 17 + kk];
            as += a;
            const float* Xr = X_s + n * 129 + d0;
            #pragma unroll
            for (int i = 0; i < 8; i++) ev[i] += a * Xr[i];
        }
        float* pe = g_partE + ((size_t)(b * 32 + tile)) * 2048 + kk * 128 + d0;
        #pragma unroll
        for (int i = 0; i < 8; i++) pe[i] = ev[i];
        if (dg == 0) g_partA[(b * 32 + tile) * 16 + kk] = as;
    }
}

// ---------------- K2: per-batch reduce -> enc + channel SE ----------------
__global__ void __launch_bounds__(256) k_reduce(
    const float* __restrict__ cw, const float* __restrict__ se_w,
    const float* __restrict__ se_b, float* __restrict__ out_enc)
{
    __shared__ float enc_s[2048];
    __shared__ float asum_s[16];
    __shared__ float red[256];
    const int b = blockIdx.x, t = threadIdx.x;
    const int base = t * 8;

    float ef[8] = {0,0,0,0,0,0,0,0};
    for (int tl = 0; tl < 32; tl++) {
        const float4* p = (const float4*)(g_partE + ((size_t)(b * 32 + tl)) * 2048 + base);
        float4 u0 = p[0], u1 = p[1];
        ef[0]+=u0.x; ef[1]+=u0.y; ef[2]+=u0.z; ef[3]+=u0.w;
        ef[4]+=u1.x; ef[5]+=u1.y; ef[6]+=u1.z; ef[7]+=u1.w;
    }
    if (t < 16) {
        float s = 0.f;
        for (int tl = 0; tl < 32; tl++) s += g_partA[(b * 32 + tl) * 16 + t];
        asum_s[t] = s;
    }
    __syncthreads();

    int k = base >> 7;
    float a = asum_s[k];
    float fin[8]; float ss = 0.f;
    #pragma unroll
    for (int i = 0; i < 8; i++) {
        fin[i] = ef[i] - a * cw[base + i];
        ss += fin[i] * fin[i];
    }
    red[t] = ss; __syncthreads();
    for (int s = 128; s > 0; s >>= 1) {
        if (t < s) red[t] += red[t + s];
        __syncthreads();
    }
    float inv = 1.f / fmaxf(sqrtf(red[0]), 1e-12f);
    #pragma unroll
    for (int i = 0; i < 8; i++) {
        float e = fin[i] * inv;
        enc_s[base + i] = e;
        out_enc[b * 2048 + base + i] = e;
    }
    __syncthreads();

    for (int c = t; c < 512; c += 256) {
        const float4* wr = (const float4*)(se_w + (size_t)c * 2048);
        float dot = 0.f;
        for (int j = 0; j < 512; j++) {
            float4 w4 = wr[j];
            const float* es = enc_s + j * 4;
            dot += es[0]*w4.x + es[1]*w4.y + es[2]*w4.z + es[3]*w4.w;
        }
        g_chn[b * 512 + c] = sigm(dot + se_b[c]);
    }
}

// ---------------- K3: out = x * spa_se * chn_se ----------------
__global__ void __launch_bounds__(256) k_out(const float* __restrict__ x, float* __restrict__ out) {
    size_t i = (size_t)blockIdx.x * 256 + threadIdx.x;  // over 8,388,608 float4
    int bi = (int)(i >> 19);             // 524288 float4 per batch
    size_t r = i & 524287;
    int c = (int)(r >> 10);              // 1024 float4 per channel
    int n4 = (int)(r & 1023);
    float4 xv = ((const float4*)x)[i];
    float4 sp = ((const float4*)g_spa)[(size_t)bi * 1024 + n4];
    float ch = g_chn[bi * 512 + c];
    float4 o;
    o.x = xv.x * sp.x * ch;
    o.y = xv.y * sp.y * ch;
    o.z = xv.z * sp.z * ch;
    o.w = xv.w * sp.w * ch;
    ((float4*)out)[i] = o;
}

// ---------------- launch ----------------
extern "C" void kernel_launch(void* const* d_in, const int* in_sizes, int n_in,
                              void* d_out, int out_size) {
    const float* x      = (const float*)d_in[0];
    const float* pre_g  = (const float*)d_in[1];
    const float* pre_b  = (const float*)d_in[2];
    const float* pre_m  = (const float*)d_in[3];
    const float* pre_v  = (const float*)d_in[4];
    const float* a1_g   = (const float*)d_in[5];
    const float* a1_b   = (const float*)d_in[6];
    const float* a1_m   = (const float*)d_in[7];
    const float* a1_v   = (const float*)d_in[8];
    const float* conv_w = (const float*)d_in[9];
    const float* conv_b = (const float*)d_in[10];
    const float* a2_g   = (const float*)d_in[11];
    const float* a2_b   = (const float*)d_in[12];
    const float* a2_m   = (const float*)d_in[13];
    const float* a2_v   = (const float*)d_in[14];
    const float* cw     = (const float*)d_in[15];
    const float* scale  = (const float*)d_in[16];
    const float* se_w   = (const float*)d_in[17];
    const float* se_b   = (const float*)d_in[18];
    const float* spa_w  = (const float*)d_in[19];
    float* out = (float*)d_out;

    const int smem_bytes = 23072 * 4;
    cudaFuncSetAttribute(k_main, cudaFuncAttributeMaxDynamicSharedMemorySize, smem_bytes);

    k_transpose_w<<<256, 256>>>(conv_w);
    k_main<<<512, 256, smem_bytes>>>(x, pre_g, pre_b, pre_m, pre_v,
                                     a1_g, a1_b, a1_m, a1_v,
                                     conv_b, a2_g, a2_b, a2_m, a2_v,
                                     cw, scale, spa_w);
    k_reduce<<<16, 256>>>(cw, se_w, se_b, out);
    k_out<<<32768, 256>>>(x, out + 32768);
}

// round 4
// speedup vs baseline: 1.1427x; 1.1427x over previous
#include <cuda_runtime.h>

#define EPSV  1e-5f
#define SLOPEV 0.01f

// ---------------- device scratch (no allocation allowed) ----------------
__device__ float g_wT[512 * 128];          // conv_w transposed: [c][d]
__device__ float g_spa[16 * 4096];         // sigmoid(spatial SE) per (b, pixel)
__device__ float g_partE[16 * 32 * 2048];  // per-(b,tile) partial E (K*D)
__device__ float g_partA[16 * 32 * 16];    // per-(b,tile) partial sum_n A
__device__ float g_chn[16 * 512];          // channel SE per (b, c)

__device__ __forceinline__ float lrelu(float v) { return v >= 0.f ? v : SLOPEV * v; }
__device__ __forceinline__ float sigm(float v) { return 1.f / (1.f + expf(-v)); }

// ---------------- K0: transpose conv_w (D=128, C=512) -> wT[c][d] ----------------
__global__ void k_transpose_w(const float* __restrict__ w) {
    int i = blockIdx.x * 256 + threadIdx.x;   // i = d*512 + c, 65536 total
    int d = i >> 9, c = i & 511;
    g_wT[c * 128 + d] = w[i];
}

// ---------------- K1: fused ABN->ABN1->conv->ABN2->encoding partials + spa ----------------
// grid = 16*32 blocks (b, tile of 128 pixels); 256 threads.
// smem layout (floats), total 23072:
//   phase B: [0,16512) X_s (128 x stride129)
//   phase A overlay of [0,16512):
//     [0,512) s0 | [512,1024) b0 | [1024,1536) s1 | [1536,2048) b1 | [2048,2560) spw
//     [2560,4672) y buf0 | [4672,6784) y buf1 | [6784,8896) w buf0 | [8896,11008) w buf1
//   [16512,18688) A_s (128 x 17)
//   [18688,20736) cw_s
//   [20736,20752) c2_s | [20752,20768) sc_s
//   [20768,20896) s2_s | [20896,21024) t2_s
//   [21024,23072) spa partials (16 x 128)
__global__ void __launch_bounds__(256, 2) k_main(
    const float* __restrict__ x,
    const float* __restrict__ pre_g, const float* __restrict__ pre_b,
    const float* __restrict__ pre_m, const float* __restrict__ pre_v,
    const float* __restrict__ a1_g, const float* __restrict__ a1_b,
    const float* __restrict__ a1_m, const float* __restrict__ a1_v,
    const float* __restrict__ conv_b,
    const float* __restrict__ a2_g, const float* __restrict__ a2_b,
    const float* __restrict__ a2_m, const float* __restrict__ a2_v,
    const float* __restrict__ cw, const float* __restrict__ scale,
    const float* __restrict__ spa_w)
{
    extern __shared__ float sm[];
    float* X_s  = sm;             // stride 129 (phase B)
    float* A_s  = sm + 16512;     // stride 17
    float* cw_s = sm + 18688;
    float* c2_s = sm + 20736;
    float* sc_s = sm + 20752;
    float* s2_s = sm + 20768;
    float* t2_s = sm + 20896;
    float* spp  = sm + 21024;
    // phase-A overlay
    float* s0_s = sm;
    float* b0_s = sm + 512;
    float* s1_s = sm + 1024;
    float* b1_s = sm + 1536;
    float* spw_s= sm + 2048;
    float* ybuf0 = sm + 2560;     // 16 x 132
    float* ybuf1 = sm + 4672;
    float* wbuf0 = sm + 6784;
    float* wbuf1 = sm + 8896;

    const int t = threadIdx.x;
    const int b = blockIdx.x >> 5;
    const int tile = blockIdx.x & 31;
    const int n0 = tile * 128;

    // ---- load constants ----
    for (int i = t; i < 512; i += 256) {
        float s0 = pre_g[i] * rsqrtf(pre_v[i] + EPSV);
        s0_s[i] = s0; b0_s[i] = pre_b[i] - pre_m[i] * s0;
        float s1 = a1_g[i] * rsqrtf(a1_v[i] + EPSV);
        s1_s[i] = s1; b1_s[i] = a1_b[i] - a1_m[i] * s1;
        spw_s[i] = spa_w[i];
    }
    if (t < 128) {
        float s2 = a2_g[t] * rsqrtf(a2_v[t] + EPSV);
        s2_s[t] = s2;
        t2_s[t] = (a2_b[t] - a2_m[t] * s2) + conv_b[t] * s2;
    }
    for (int i = t; i < 2048; i += 256) cw_s[i] = cw[i];
    if (t < 16) {
        float c2 = 0.f;
        for (int d = 0; d < 128; d++) { float v = cw[t * 128 + d]; c2 += v * v; }
        c2_s[t] = c2; sc_s[t] = scale[t];
    }

    const int tx = t & 15;   // pixel group (8 pixels)
    const int ty = t >> 4;   // d group (8 d's) AND channel-in-chunk for loads

    const float* xbase = x + ((size_t)b * 512) * 4096 + n0 + tx * 8;

    float4 xv0, xv1, wv0, wv1;           // prefetch registers
    float spa_acc[8] = {0,0,0,0,0,0,0,0};

    // chunk kc covers channels kc*16+ty
    #define LOAD_CHUNK(kc) do { \
        int c_ = (kc) * 16 + ty; \
        const float4* xp_ = (const float4*)(xbase + (size_t)c_ * 4096); \
        xv0 = xp_[0]; xv1 = xp_[1]; \
        const float4* wp_ = (const float4*)(g_wT + (size_t)c_ * 128 + tx * 8); \
        wv0 = wp_[0]; wv1 = wp_[1]; \
    } while (0)

    #define STORE_CHUNK(yq, wq, kc) do { \
        int c_ = (kc) * 16 + ty; \
        float s0_ = s0_s[c_], b0_ = b0_s[c_], s1_ = s1_s[c_], b1_ = b1_s[c_], sw_ = spw_s[c_]; \
        float xr_[8] = {xv0.x, xv0.y, xv0.z, xv0.w, xv1.x, xv1.y, xv1.z, xv1.w}; \
        float yr_[8]; \
        _Pragma("unroll") \
        for (int j_ = 0; j_ < 8; j_++) { \
            float p_ = lrelu(xr_[j_] * s0_ + b0_); \
            spa_acc[j_] += sw_ * p_; \
            yr_[j_] = lrelu(p_ * s1_ + b1_); \
        } \
        float4* yrow_ = (float4*)((yq) + ty * 132 + tx * 8); \
        yrow_[0] = make_float4(yr_[0], yr_[1], yr_[2], yr_[3]); \
        yrow_[1] = make_float4(yr_[4], yr_[5], yr_[6], yr_[7]); \
        float4* wrow_ = (float4*)((wq) + ty * 132 + tx * 8); \
        wrow_[0] = wv0; wrow_[1] = wv1; \
    } while (0)

    // prologue: fill buf0 with chunk 0, prefetch chunk 1
    LOAD_CHUNK(0);
    __syncthreads();                    // constants ready
    STORE_CHUNK(ybuf0, wbuf0, 0);
    LOAD_CHUNK(1);
    __syncthreads();                    // buf0 visible

    unsigned long long acc2[8][4];
    #pragma unroll
    for (int i = 0; i < 8; i++)
        #pragma unroll
        for (int j = 0; j < 4; j++) acc2[i][j] = 0ull;

    int pb = 0;
    for (int kc = 0; kc < 32; kc++) {
        const float* yc = pb ? ybuf1 : ybuf0;
        const float* wc = pb ? wbuf1 : wbuf0;
        // ---- compute 16 k-steps with packed f32x2 FMA ----
        #pragma unroll
        for (int k = 0; k < 16; k++) {
            unsigned long long w2[8];
            #pragma unroll
            for (int i = 0; i < 8; i++) {
                unsigned int wr = __float_as_uint(wc[k * 132 + ty * 8 + i]);
                asm("mov.b64 %0, {%1, %1};" : "=l"(w2[i]) : "r"(wr));
            }
            unsigned long long y2[4];
            #pragma unroll
            for (int j = 0; j < 4; j++)
                y2[j] = *(const unsigned long long*)(yc + k * 132 + tx * 8 + j * 2);
            #pragma unroll
            for (int i = 0; i < 8; i++)
                #pragma unroll
                for (int j = 0; j < 4; j++)
                    asm("fma.rn.f32x2 %0, %1, %2, %0;" : "+l"(acc2[i][j]) : "l"(w2[i]), "l"(y2[j]));
        }
        // ---- refill the idle buffer with chunk kc+1 (regs already hold it) ----
        if (kc < 31) {
            float* yn = pb ? ybuf0 : ybuf1;
            float* wn = pb ? wbuf0 : wbuf1;
            STORE_CHUNK(yn, wn, kc + 1);
            if (kc < 30) LOAD_CHUNK(kc + 2);   // overlap LDG with next compute
        }
        __syncthreads();
        pb ^= 1;
    }
    #undef LOAD_CHUNK
    #undef STORE_CHUNK

    // ---- ABN2 -> X_s, spa partials ----
    #pragma unroll
    for (int i = 0; i < 8; i++) {
        int d = ty * 8 + i;
        float s2 = s2_s[d], t2 = t2_s[d];
        #pragma unroll
        for (int j = 0; j < 4; j++) {
            unsigned int lo, hi;
            asm("mov.b64 {%0, %1}, %2;" : "=r"(lo), "=r"(hi) : "l"(acc2[i][j]));
            int n = tx * 8 + j * 2;
            X_s[n * 129 + d]       = lrelu(__uint_as_float(lo) * s2 + t2);
            X_s[(n + 1) * 129 + d] = lrelu(__uint_as_float(hi) * s2 + t2);
        }
    }
    #pragma unroll
    for (int j = 0; j < 8; j++) spp[ty * 128 + tx * 8 + j] = spa_acc[j];
    __syncthreads();

    if (t < 128) {
        float s = 0.f;
        #pragma unroll
        for (int r = 0; r < 16; r++) s += spp[r * 128 + t];
        g_spa[b * 4096 + n0 + t] = sigm(s);
    }

    // ---- per-pixel scaled-L2 softmax -> A_s ----
    if (t < 128) {
        const float* Xr = X_s + t * 129;
        float x2 = 0.f;
        for (int d = 0; d < 128; d++) { float xv = Xr[d]; x2 += xv * xv; }
        float e[16]; float mx = -1e30f;
        #pragma unroll
        for (int k = 0; k < 16; k++) {
            float dot = 0.f;
            const float* cwr = cw_s + k * 128;
            for (int d = 0; d < 128; d++) dot += Xr[d] * cwr[d];
            float sl = sc_s[k] * (x2 - 2.f * dot + c2_s[k]);
            e[k] = sl; mx = fmaxf(mx, sl);
        }
        float sum = 0.f;
        #pragma unroll
        for (int k = 0; k < 16; k++) { e[k] = expf(e[k] - mx); sum += e[k]; }
        float inv = 1.f / sum;
        #pragma unroll
        for (int k = 0; k < 16; k++) A_s[t * 17 + k] = e[k] * inv;
    }
    __syncthreads();

    // ---- partial E (K x D) and asum ----
    {
        int kk = t >> 4;        // 0..15
        int dg = t & 15;        // 0..15
        int d0 = dg * 8;
        float ev[8] = {0,0,0,0,0,0,0,0};
        float as = 0.f;
        for (int n = 0; n < 128; n++) {
            float a = A_s[n * 17 + kk];
            as += a;
            const float* Xr = X_s + n * 129 + d0;
            #pragma unroll
            for (int i = 0; i < 8; i++) ev[i] += a * Xr[i];
        }
        float* pe = g_partE + ((size_t)(b * 32 + tile)) * 2048 + kk * 128 + d0;
        #pragma unroll
        for (int i = 0; i < 8; i++) pe[i] = ev[i];
        if (dg == 0) g_partA[(b * 32 + tile) * 16 + kk] = as;
    }
}

// ---------------- K2: per-batch reduce -> enc + channel SE ----------------
__global__ void __launch_bounds__(256) k_reduce(
    const float* __restrict__ cw, const float* __restrict__ se_w,
    const float* __restrict__ se_b, float* __restrict__ out_enc)
{
    __shared__ float enc_s[2048];
    __shared__ float asum_s[16];
    __shared__ float red[256];
    const int b = blockIdx.x, t = threadIdx.x;
    const int base = t * 8;

    float ef[8] = {0,0,0,0,0,0,0,0};
    for (int tl = 0; tl < 32; tl++) {
        const float4* p = (const float4*)(g_partE + ((size_t)(b * 32 + tl)) * 2048 + base);
        float4 u0 = p[0], u1 = p[1];
        ef[0]+=u0.x; ef[1]+=u0.y; ef[2]+=u0.z; ef[3]+=u0.w;
        ef[4]+=u1.x; ef[5]+=u1.y; ef[6]+=u1.z; ef[7]+=u1.w;
    }
    if (t < 16) {
        float s = 0.f;
        for (int tl = 0; tl < 32; tl++) s += g_partA[(b * 32 + tl) * 16 + t];
        asum_s[t] = s;
    }
    __syncthreads();

    int k = base >> 7;
    float a = asum_s[k];
    float fin[8]; float ss = 0.f;
    #pragma unroll
    for (int i = 0; i < 8; i++) {
        fin[i] = ef[i] - a * cw[base + i];
        ss += fin[i] * fin[i];
    }
    red[t] = ss; __syncthreads();
    for (int s = 128; s > 0; s >>= 1) {
        if (t < s) red[t] += red[t + s];
        __syncthreads();
    }
    float inv = 1.f / fmaxf(sqrtf(red[0]), 1e-12f);
    #pragma unroll
    for (int i = 0; i < 8; i++) {
        float e = fin[i] * inv;
        enc_s[base + i] = e;
        out_enc[b * 2048 + base + i] = e;
    }
    __syncthreads();

    for (int c = t; c < 512; c += 256) {
        const float4* wr = (const float4*)(se_w + (size_t)c * 2048);
        float dot = 0.f;
        for (int j = 0; j < 512; j++) {
            float4 w4 = wr[j];
            const float* es = enc_s + j * 4;
            dot += es[0]*w4.x + es[1]*w4.y + es[2]*w4.z + es[3]*w4.w;
        }
        g_chn[b * 512 + c] = sigm(dot + se_b[c]);
    }
}

// ---------------- K3: out = x * spa_se * chn_se ----------------
__global__ void __launch_bounds__(256) k_out(const float* __restrict__ x, float* __restrict__ out) {
    size_t i = (size_t)blockIdx.x * 256 + threadIdx.x;  // over 8,388,608 float4
    int bi = (int)(i >> 19);             // 524288 float4 per batch
    size_t r = i & 524287;
    int c = (int)(r >> 10);              // 1024 float4 per channel
    int n4 = (int)(r & 1023);
    float4 xv = ((const float4*)x)[i];
    float4 sp = ((const float4*)g_spa)[(size_t)bi * 1024 + n4];
    float ch = g_chn[bi * 512 + c];
    float4 o;
    o.x = xv.x * sp.x * ch;
    o.y = xv.y * sp.y * ch;
    o.z = xv.z * sp.z * ch;
    o.w = xv.w * sp.w * ch;
    ((float4*)out)[i] = o;
}

// ---------------- launch ----------------
extern "C" void kernel_launch(void* const* d_in, const int* in_sizes, int n_in,
                              void* d_out, int out_size) {
    const float* x      = (const float*)d_in[0];
    const float* pre_g  = (const float*)d_in[1];
    const float* pre_b  = (const float*)d_in[2];
    const float* pre_m  = (const float*)d_in[3];
    const float* pre_v  = (const float*)d_in[4];
    const float* a1_g   = (const float*)d_in[5];
    const float* a1_b   = (const float*)d_in[6];
    const float* a1_m   = (const float*)d_in[7];
    const float* a1_v   = (const float*)d_in[8];
    const float* conv_w = (const float*)d_in[9];
    const float* conv_b = (const float*)d_in[10];
    const float* a2_g   = (const float*)d_in[11];
    const float* a2_b   = (const float*)d_in[12];
    const float* a2_m   = (const float*)d_in[13];
    const float* a2_v   = (const float*)d_in[14];
    const float* cw     = (const float*)d_in[15];
    const float* scale  = (const float*)d_in[16];
    const float* se_w   = (const float*)d_in[17];
    const float* se_b   = (const float*)d_in[18];
    const float* spa_w  = (const float*)d_in[19];
    float* out = (float*)d_out;

    const int smem_bytes = 23072 * 4;
    cudaFuncSetAttribute(k_main, cudaFuncAttributeMaxDynamicSharedMemorySize, smem_bytes);

    k_transpose_w<<<256, 256>>>(conv_w);
    k_main<<<512, 256, smem_bytes>>>(x, pre_g, pre_b, pre_m, pre_v,
                                     a1_g, a1_b, a1_m, a1_v,
                                     conv_b, a2_g, a2_b, a2_m, a2_v,
                                     cw, scale, spa_w);
    k_reduce<<<16, 256>>>(cw, se_w, se_b, out);
    k_out<<<32768, 256>>>(x, out + 32768);
}

// round 11
// speedup vs baseline: 1.1725x; 1.0261x over previous
#include <cuda_runtime.h>
#include <cuda_bf16.h>
#include <cstdint>

#define EPSV  1e-5f
#define SLOPEV 0.01f

// ---------------- device scratch (no allocation allowed) ----------------
__device__ __align__(16) __nv_bfloat16 g_wh[128 * 512];  // bf16 hi of conv_w [d][c]
__device__ __align__(16) __nv_bfloat16 g_wl[128 * 512];  // bf16 lo of conv_w [d][c]
__device__ float g_spa[16 * 4096];         // sigmoid(spatial SE) per (b, pixel)
__device__ float g_partE[16 * 32 * 2048];  // per-(b,tile) partial E (K*D)
__device__ float g_partA[16 * 32 * 16];    // per-(b,tile) partial sum_n A
__device__ float g_chn[16 * 512];          // channel SE per (b, c)

__device__ __forceinline__ float lrelu(float v) { return v >= 0.f ? v : SLOPEV * v; }
__device__ __forceinline__ float sigm(float v) { return 1.f / (1.f + expf(-v)); }

__device__ __forceinline__ unsigned pack2(float lo, float hi) {
    unsigned r;
    asm("cvt.rn.bf16x2.f32 %0, %1, %2;" : "=r"(r) : "f"(hi), "f"(lo));
    return r;
}
__device__ __forceinline__ uint32_t smem_to_u32(const void* p) {
    uint32_t a;
    asm("{ .reg .u64 tmp; cvta.to.shared.u64 tmp, %1; cvt.u32.u64 %0, tmp; }" : "=r"(a) : "l"(p));
    return a;
}

// ldmatrix x4 (four 8x8 b16 matrices; reg i fed by lanes 8i..8i+7's addresses)
#define LDSM4(r, addr) \
    asm volatile("ldmatrix.sync.aligned.m8n8.x4.shared.b16 {%0,%1,%2,%3}, [%4];" \
        : "=r"((r)[0]), "=r"((r)[1]), "=r"((r)[2]), "=r"((r)[3]) : "r"(addr))

// D += A(16x16 bf16, row) x B(16x8 bf16, col)  fp32 accumulate
#define MMA16816(d, a, b0, b1) \
    asm volatile("mma.sync.aligned.m16n8k16.row.col.f32.bf16.bf16.f32 " \
        "{%0,%1,%2,%3}, {%4,%5,%6,%7}, {%8,%9}, {%0,%1,%2,%3};" \
        : "+f"((d)[0]), "+f"((d)[1]), "+f"((d)[2]), "+f"((d)[3]) \
        : "r"((a)[0]), "r"((a)[1]), "r"((a)[2]), "r"((a)[3]), "r"(b0), "r"(b1))

// ---------------- K0: split conv_w into bf16 hi/lo ----------------
__global__ void k_split_w(const float* __restrict__ w) {
    int i = blockIdx.x * 256 + threadIdx.x;    // 65536 elements, [d][c] layout
    float v = w[i];
    __nv_bfloat16 h = __float2bfloat16(v);
    g_wh[i] = h;
    g_wl[i] = __float2bfloat16(v - __bfloat162float(h));
}

// ---------------- K1 smem layout ----------------
// floats:
//  [0,128) s2 | [128,256) t2 | [256,2304) cw_s | [2304,2320) c2 | [2320,2336) sc
//  [2336,4384) spp (16x128)
//  overlay (production): s0[4384) b0[4896) s1[5408) b1[5920) spw[6432..6944)
//    bf16 tiles (byte offsets): YH 28672 | YL 47104 | WH 65536 | WL 83968 .. 102400
//    tile = 128 rows x 72 bf16 (stride 144 B)
//  overlay (epilogue): X_s floats [4384,20896) stride 129 | A_s [20896,23072) stride 17
#define SM_BYTES 102400
#define TS 144              // tile row stride in bytes (72 bf16)
#define YH_B 28672
#define YL_B 47104
#define WH_B 65536
#define WL_B 83968

__global__ void __launch_bounds__(256) k_main(
    const float* __restrict__ x,
    const float* __restrict__ pre_g, const float* __restrict__ pre_b,
    const float* __restrict__ pre_m, const float* __restrict__ pre_v,
    const float* __restrict__ a1_g, const float* __restrict__ a1_b,
    const float* __restrict__ a1_m, const float* __restrict__ a1_v,
    const float* __restrict__ conv_b,
    const float* __restrict__ a2_g, const float* __restrict__ a2_b,
    const float* __restrict__ a2_m, const float* __restrict__ a2_v,
    const float* __restrict__ cw, const float* __restrict__ scale,
    const float* __restrict__ spa_w)
{
    extern __shared__ float sm[];
    char* smb = (char*)sm;
    float* s2_s = sm;
    float* t2_s = sm + 128;
    float* cw_s = sm + 256;
    float* c2_s = sm + 2304;
    float* sc_s = sm + 2320;
    float* spp  = sm + 2336;
    float* s0_s = sm + 4384;
    float* b0_s = sm + 4896;
    float* s1_s = sm + 5408;
    float* b1_s = sm + 5920;
    float* spw_s= sm + 6432;
    float* X_s  = sm + 4384;      // stride 129 (epilogue)
    float* A_s  = sm + 20896;     // stride 17  (epilogue)

    const uint32_t smem_u = smem_to_u32(sm);

    const int t = threadIdx.x;
    const int wid = t >> 5;
    const int lane = t & 31;
    const int b = blockIdx.x >> 5;
    const int tile = blockIdx.x & 31;
    const int n0 = tile * 128;
    const int tx = t & 15;
    const int ty = t >> 4;

    // ---- constants ----
    for (int i = t; i < 512; i += 256) {
        float s0 = pre_g[i] * rsqrtf(pre_v[i] + EPSV);
        s0_s[i] = s0; b0_s[i] = pre_b[i] - pre_m[i] * s0;
        float s1 = a1_g[i] * rsqrtf(a1_v[i] + EPSV);
        s1_s[i] = s1; b1_s[i] = a1_b[i] - a1_m[i] * s1;
        spw_s[i] = spa_w[i];
    }
    if (t < 128) {
        float s2 = a2_g[t] * rsqrtf(a2_v[t] + EPSV);
        s2_s[t] = s2;
        t2_s[t] = (a2_b[t] - a2_m[t] * s2) + conv_b[t] * s2;
    }
    for (int i = t; i < 2048; i += 256) cw_s[i] = cw[i];
    if (t < 16) {
        float c2 = 0.f;
        for (int d = 0; d < 128; d++) { float v = cw[t * 128 + d]; c2 += v * v; }
        c2_s[t] = c2; sc_s[t] = scale[t];
    }
    __syncthreads();

    // warp roles: mg = d-group (32 d), ngrp = n-half (64 n)
    const int mg = wid & 3;
    const int ngrp = wid >> 2;
    const int d_base = mg * 32;
    const int n_base = ngrp * 64;

    // ldmatrix lane address components
    const int arow = (lane & 7) + ((lane >> 3) & 1) * 8;   // A: row within m16 tile
    const int acol = ((lane >> 4) & 1) * 8;                // A: k offset (bf16)
    const int brow = (lane & 7) + ((lane >> 4) & 1) * 8;   // B: row within n16 pair
    const int bcol = ((lane >> 3) & 1) * 8;                // B: k offset

    float acc[2][8][4];
    #pragma unroll
    for (int mt = 0; mt < 2; mt++)
        #pragma unroll
        for (int nt = 0; nt < 8; nt++)
            #pragma unroll
            for (int q = 0; q < 4; q++) acc[mt][nt][q] = 0.f;

    float spa_acc[8] = {0,0,0,0,0,0,0,0};
    const float* xcol = x + ((size_t)b * 512 + ty * 4) * 4096 + n0 + tx;

    for (int ci = 0; ci < 8; ci++) {
        const int c0 = ci * 64;
        // ---- copy w chunk hi/lo [128 d][64 c] ----
        #pragma unroll
        for (int it = 0; it < 4; it++) {
            int idx = t + it * 256;          // 0..1023
            int d = idx >> 3, q = idx & 7;
            int dst = d * TS + q * 16;
            *(uint4*)(smb + WH_B + dst) = *(const uint4*)(g_wh + d * 512 + c0 + q * 8);
            *(uint4*)(smb + WL_B + dst) = *(const uint4*)(g_wl + d * 512 + c0 + q * 8);
        }
        // ---- produce y chunk: thread = 4 channels x 8 pixels ----
        {
            int cc = c0 + ty * 4;
            float s0v[4], b0v[4], s1v[4], b1v[4], swv[4];
            #pragma unroll
            for (int i = 0; i < 4; i++) {
                s0v[i] = s0_s[cc + i]; b0v[i] = b0_s[cc + i];
                s1v[i] = s1_s[cc + i]; b1v[i] = b1_s[cc + i];
                swv[i] = spw_s[cc + i];
            }
            const float* xr = xcol + (size_t)c0 * 4096;
            #pragma unroll
            for (int j = 0; j < 8; j++) {
                int n = tx + 16 * j;
                float yh[4], yl[4];
                #pragma unroll
                for (int i = 0; i < 4; i++) {
                    float xv = xr[(size_t)i * 4096 + 16 * j];
                    float p = lrelu(xv * s0v[i] + b0v[i]);
                    spa_acc[j] += swv[i] * p;
                    float y = lrelu(p * s1v[i] + b1v[i]);
                    float h = __bfloat162float(__float2bfloat16(y));
                    yh[i] = h; yl[i] = y - h;
                }
                unsigned h0 = pack2(yh[0], yh[1]), h1 = pack2(yh[2], yh[3]);
                unsigned l0 = pack2(yl[0], yl[1]), l1 = pack2(yl[2], yl[3]);
                unsigned long long hv = (unsigned long long)h0 | ((unsigned long long)h1 << 32);
                unsigned long long lv = (unsigned long long)l0 | ((unsigned long long)l1 << 32);
                int off = n * TS + ty * 8;
                *(unsigned long long*)(smb + YH_B + off) = hv;
                *(unsigned long long*)(smb + YL_B + off) = lv;
            }
        }
        __syncthreads();

        // ---- MMA: 4 k16-steps x (hh + hl + lh) ----
        #pragma unroll
        for (int ks = 0; ks < 4; ks++) {
            const int kb = (ks * 16) * 2;   // k byte offset base
            uint32_t ah[2][4], al[2][4];
            #pragma unroll
            for (int mt = 0; mt < 2; mt++) {
                uint32_t aoff = (d_base + mt * 16 + arow) * TS + kb + acol * 2;
                LDSM4(ah[mt], smem_u + WH_B + aoff);
                LDSM4(al[mt], smem_u + WL_B + aoff);
            }
            #pragma unroll
            for (int p = 0; p < 4; p++) {
                uint32_t bh[4], bl[4];
                uint32_t boff = (n_base + p * 16 + brow) * TS + kb + bcol * 2;
                LDSM4(bh, smem_u + YH_B + boff);
                LDSM4(bl, smem_u + YL_B + boff);
                #pragma unroll
                for (int mt = 0; mt < 2; mt++) {
                    MMA16816(acc[mt][2*p],   ah[mt], bh[0], bh[1]);
                    MMA16816(acc[mt][2*p+1], ah[mt], bh[2], bh[3]);
                    MMA16816(acc[mt][2*p],   ah[mt], bl[0], bl[1]);
                    MMA16816(acc[mt][2*p+1], ah[mt], bl[2], bl[3]);
                    MMA16816(acc[mt][2*p],   al[mt], bh[0], bh[1]);
                    MMA16816(acc[mt][2*p+1], al[mt], bh[2], bh[3]);
                }
            }
        }
        __syncthreads();
    }

    // ---- spa partials ----
    #pragma unroll
    for (int j = 0; j < 8; j++) spp[ty * 128 + tx + 16 * j] = spa_acc[j];

    // ---- epilogue: acc -> ABN2 -> X_s[n][d] (stride 129) ----
    {
        int dl = lane >> 2;           // 0..7
        int nl = (lane & 3) * 2;      // 0,2,4,6
        #pragma unroll
        for (int mt = 0; mt < 2; mt++) {
            int d0 = d_base + mt * 16 + dl;
            float s2a = s2_s[d0],     t2a = t2_s[d0];
            float s2b = s2_s[d0 + 8], t2b = t2_s[d0 + 8];
            #pragma unroll
            for (int nt = 0; nt < 8; nt++) {
                int nv = n_base + nt * 8 + nl;
                X_s[nv * 129 + d0]           = lrelu(acc[mt][nt][0] * s2a + t2a);
                X_s[(nv + 1) * 129 + d0]     = lrelu(acc[mt][nt][1] * s2a + t2a);
                X_s[nv * 129 + d0 + 8]       = lrelu(acc[mt][nt][2] * s2b + t2b);
                X_s[(nv + 1) * 129 + d0 + 8] = lrelu(acc[mt][nt][3] * s2b + t2b);
            }
        }
    }
    __syncthreads();

    if (t < 128) {
        float s = 0.f;
        #pragma unroll
        for (int r = 0; r < 16; r++) s += spp[r * 128 + t];
        g_spa[b * 4096 + n0 + t] = sigm(s);
    }

    // ---- per-pixel scaled-L2 softmax -> A_s ----
    if (t < 128) {
        const float* Xr = X_s + t * 129;
        float x2 = 0.f;
        for (int d = 0; d < 128; d++) { float xv = Xr[d]; x2 += xv * xv; }
        float e[16]; float mx = -1e30f;
        #pragma unroll
        for (int k = 0; k < 16; k++) {
            float dot = 0.f;
            const float* cwr = cw_s + k * 128;
            for (int d = 0; d < 128; d++) dot += Xr[d] * cwr[d];
            float sl = sc_s[k] * (x2 - 2.f * dot + c2_s[k]);
            e[k] = sl; mx = fmaxf(mx, sl);
        }
        float sum = 0.f;
        #pragma unroll
        for (int k = 0; k < 16; k++) { e[k] = expf(e[k] - mx); sum += e[k]; }
        float inv = 1.f / sum;
        #pragma unroll
        for (int k = 0; k < 16; k++) A_s[t * 17 + k] = e[k] * inv;
    }
    __syncthreads();

    // ---- partial E (K x D) and asum ----
    {
        int kk = t >> 4;
        int dg = t & 15;
        int d0 = dg * 8;
        float ev[8] = {0,0,0,0,0,0,0,0};
        float as = 0.f;
        for (int n = 0; n < 128; n++) {
            float a = A_s[n * 17 + kk];
            as += a;
            const float* Xr = X_s + n * 129 + d0;
            #pragma unroll
            for (int i = 0; i < 8; i++) ev[i] += a * Xr[i];
        }
        float* pe = g_partE + ((size_t)(b * 32 + tile)) * 2048 + kk * 128 + d0;
        #pragma unroll
        for (int i = 0; i < 8; i++) pe[i] = ev[i];
        if (dg == 0) g_partA[(b * 32 + tile) * 16 + kk] = as;
    }
}

// ---------------- K2: per-batch reduce -> enc + channel SE ----------------
__global__ void __launch_bounds__(256) k_reduce(
    const float* __restrict__ cw, const float* __restrict__ se_w,
    const float* __restrict__ se_b, float* __restrict__ out_enc)
{
    __shared__ float enc_s[2048];
    __shared__ float asum_s[16];
    __shared__ float red[256];
    const int b = blockIdx.x, t = threadIdx.x;
    const int base = t * 8;

    float ef[8] = {0,0,0,0,0,0,0,0};
    for (int tl = 0; tl < 32; tl++) {
        const float4* p = (const float4*)(g_partE + ((size_t)(b * 32 + tl)) * 2048 + base);
        float4 u0 = p[0], u1 = p[1];
        ef[0]+=u0.x; ef[1]+=u0.y; ef[2]+=u0.z; ef[3]+=u0.w;
        ef[4]+=u1.x; ef[5]+=u1.y; ef[6]+=u1.z; ef[7]+=u1.w;
    }
    if (t < 16) {
        float s = 0.f;
        for (int tl = 0; tl < 32; tl++) s += g_partA[(b * 32 + tl) * 16 + t];
        asum_s[t] = s;
    }
    __syncthreads();

    int k = base >> 7;
    float a = asum_s[k];
    float fin[8]; float ss = 0.f;
    #pragma unroll
    for (int i = 0; i < 8; i++) {
        fin[i] = ef[i] - a * cw[base + i];
        ss += fin[i] * fin[i];
    }
    red[t] = ss; __syncthreads();
    for (int s = 128; s > 0; s >>= 1) {
        if (t < s) red[t] += red[t + s];
        __syncthreads();
    }
    float inv = 1.f / fmaxf(sqrtf(red[0]), 1e-12f);
    #pragma unroll
    for (int i = 0; i < 8; i++) {
        float e = fin[i] * inv;
        enc_s[base + i] = e;
        out_enc[b * 2048 + base + i] = e;
    }
    __syncthreads();

    for (int c = t; c < 512; c += 256) {
        const float4* wr = (const float4*)(se_w + (size_t)c * 2048);
        float dot = 0.f;
        for (int j = 0; j < 512; j++) {
            float4 w4 = wr[j];
            const float* es = enc_s + j * 4;
            dot += es[0]*w4.x + es[1]*w4.y + es[2]*w4.z + es[3]*w4.w;
        }
        g_chn[b * 512 + c] = sigm(dot + se_b[c]);
    }
}

// ---------------- K3: out = x * spa_se * chn_se ----------------
__global__ void __launch_bounds__(256) k_out(const float* __restrict__ x, float* __restrict__ out) {
    size_t i = (size_t)blockIdx.x * 256 + threadIdx.x;  // over 8,388,608 float4
    int bi = (int)(i >> 19);
    size_t r = i & 524287;
    int c = (int)(r >> 10);
    int n4 = (int)(r & 1023);
    float4 xv = ((const float4*)x)[i];
    float4 sp = ((const float4*)g_spa)[(size_t)bi * 1024 + n4];
    float ch = g_chn[bi * 512 + c];
    float4 o;
    o.x = xv.x * sp.x * ch;
    o.y = xv.y * sp.y * ch;
    o.z = xv.z * sp.z * ch;
    o.w = xv.w * sp.w * ch;
    ((float4*)out)[i] = o;
}

// ---------------- launch ----------------
extern "C" void kernel_launch(void* const* d_in, const int* in_sizes, int n_in,
                              void* d_out, int out_size) {
    const float* x      = (const float*)d_in[0];
    const float* pre_g  = (const float*)d_in[1];
    const float* pre_b  = (const float*)d_in[2];
    const float* pre_m  = (const float*)d_in[3];
    const float* pre_v  = (const float*)d_in[4];
    const float* a1_g   = (const float*)d_in[5];
    const float* a1_b   = (const float*)d_in[6];
    const float* a1_m   = (const float*)d_in[7];
    const float* a1_v   = (const float*)d_in[8];
    const float* conv_w = (const float*)d_in[9];
    const float* conv_b = (const float*)d_in[10];
    const float* a2_g   = (const float*)d_in[11];
    const float* a2_b   = (const float*)d_in[12];
    const float* a2_m   = (const float*)d_in[13];
    const float* a2_v   = (const float*)d_in[14];
    const float* cw     = (const float*)d_in[15];
    const float* scale  = (const float*)d_in[16];
    const float* se_w   = (const float*)d_in[17];
    const float* se_b   = (const float*)d_in[18];
    const float* spa_w  = (const float*)d_in[19];
    float* out = (float*)d_out;

    cudaFuncSetAttribute(k_main, cudaFuncAttributeMaxDynamicSharedMemorySize, SM_BYTES);

    k_split_w<<<256, 256>>>(conv_w);
    k_main<<<512, 256, SM_BYTES>>>(x, pre_g, pre_b, pre_m, pre_v,
                                   a1_g, a1_b, a1_m, a1_v,
                                   conv_b, a2_g, a2_b, a2_m, a2_v,
                                   cw, scale, spa_w);
    k_reduce<<<16, 256>>>(cw, se_w, se_b, out);
    k_out<<<32768, 256>>>(x, out + 32768);
}

// round 16
// speedup vs baseline: 1.5207x; 1.2970x over previous
#include <cuda_runtime.h>
#include <cuda_bf16.h>
#include <cstdint>

#define EPSV  1e-5f
#define SLOPEV 0.01f

// ---------------- device scratch (no allocation allowed) ----------------
__device__ __align__(16) __nv_bfloat16 g_wh[128 * 512];  // bf16 hi of conv_w [d][c]
__device__ __align__(16) __nv_bfloat16 g_wl[128 * 512];  // bf16 lo of conv_w [d][c]
__device__ __align__(16) float g_X[16 * 128 * 4096];     // X [b][d][n]  (32 MB)
__device__ float g_spa[16 * 4096];         // sigmoid(spatial SE) per (b, pixel)
__device__ float g_partE[16 * 32 * 2048];  // per-(b,tile) partial E (K*D)
__device__ float g_partA[16 * 32 * 16];    // per-(b,tile) partial sum_n A
__device__ float g_enc[16 * 2048];         // normalized enc
__device__ float g_chn[16 * 512];          // channel SE per (b, c)

__device__ __forceinline__ float lrelu(float v) { return v >= 0.f ? v : SLOPEV * v; }
__device__ __forceinline__ float sigm(float v) { return 1.f / (1.f + expf(-v)); }

__device__ __forceinline__ unsigned pack2(float lo, float hi) {
    unsigned r;
    asm("cvt.rn.bf16x2.f32 %0, %1, %2;" : "=r"(r) : "f"(hi), "f"(lo));
    return r;
}
__device__ __forceinline__ uint32_t smem_to_u32(const void* p) {
    uint32_t a;
    asm("{ .reg .u64 tmp; cvta.to.shared.u64 tmp, %1; cvt.u32.u64 %0, tmp; }" : "=r"(a) : "l"(p));
    return a;
}

#define LDSM4(r, addr) \
    asm volatile("ldmatrix.sync.aligned.m8n8.x4.shared.b16 {%0,%1,%2,%3}, [%4];" \
        : "=r"((r)[0]), "=r"((r)[1]), "=r"((r)[2]), "=r"((r)[3]) : "r"(addr))

#define MMA16816(d, a, b0, b1) \
    asm volatile("mma.sync.aligned.m16n8k16.row.col.f32.bf16.bf16.f32 " \
        "{%0,%1,%2,%3}, {%4,%5,%6,%7}, {%8,%9}, {%0,%1,%2,%3};" \
        : "+f"((d)[0]), "+f"((d)[1]), "+f"((d)[2]), "+f"((d)[3]) \
        : "r"((a)[0]), "r"((a)[1]), "r"((a)[2]), "r"((a)[3]), "r"(b0), "r"(b1))

// ---------------- K0: split conv_w into bf16 hi/lo ----------------
__global__ void k_split_w(const float* __restrict__ w) {
    int i = blockIdx.x * 256 + threadIdx.x;
    float v = w[i];
    __nv_bfloat16 h = __float2bfloat16(v);
    g_wh[i] = h;
    g_wl[i] = __float2bfloat16(v - __bfloat162float(h));
}

// ---------------- K1: k_gemm — ABN+ABN1 -> HMMA conv -> ABN2 -> X global, spa ----------------
// smem floats: s2[0,128) t2[128,256) spp[256,2304) s0[2304,2816) b0[2816,3328)
//              s1[3328,3840) b1[3840,4352) spw[4352,4864)
// tiles (bytes): YH 20480 | YL 38912 | WH 57344 | WL 75776 .. 94208 (128 rows x 144B)
#define SMG_BYTES 94208
#define TS 144
#define YH_B 20480
#define YL_B 38912
#define WH_B 57344
#define WL_B 75776

__global__ void __launch_bounds__(256) k_gemm(
    const float* __restrict__ x,
    const float* __restrict__ pre_g, const float* __restrict__ pre_b,
    const float* __restrict__ pre_m, const float* __restrict__ pre_v,
    const float* __restrict__ a1_g, const float* __restrict__ a1_b,
    const float* __restrict__ a1_m, const float* __restrict__ a1_v,
    const float* __restrict__ conv_b,
    const float* __restrict__ a2_g, const float* __restrict__ a2_b,
    const float* __restrict__ a2_m, const float* __restrict__ a2_v,
    const float* __restrict__ spa_w)
{
    extern __shared__ float sm[];
    char* smb = (char*)sm;
    float* s2_s = sm;
    float* t2_s = sm + 128;
    float* spp  = sm + 256;
    float* s0_s = sm + 2304;
    float* b0_s = sm + 2816;
    float* s1_s = sm + 3328;
    float* b1_s = sm + 3840;
    float* spw_s= sm + 4352;

    const uint32_t smem_u = smem_to_u32(sm);
    const int t = threadIdx.x;
    const int wid = t >> 5;
    const int lane = t & 31;
    const int b = blockIdx.x >> 5;
    const int tile = blockIdx.x & 31;
    const int n0 = tile * 128;
    const int tx = t & 15;
    const int ty = t >> 4;

    for (int i = t; i < 512; i += 256) {
        float s0 = pre_g[i] * rsqrtf(pre_v[i] + EPSV);
        s0_s[i] = s0; b0_s[i] = pre_b[i] - pre_m[i] * s0;
        float s1 = a1_g[i] * rsqrtf(a1_v[i] + EPSV);
        s1_s[i] = s1; b1_s[i] = a1_b[i] - a1_m[i] * s1;
        spw_s[i] = spa_w[i];
    }
    if (t < 128) {
        float s2 = a2_g[t] * rsqrtf(a2_v[t] + EPSV);
        s2_s[t] = s2;
        t2_s[t] = (a2_b[t] - a2_m[t] * s2) + conv_b[t] * s2;
    }
    __syncthreads();

    const int mg = wid & 3;
    const int ngrp = wid >> 2;
    const int d_base = mg * 32;
    const int n_base = ngrp * 64;

    const int arow = (lane & 7) + ((lane >> 3) & 1) * 8;
    const int acol = ((lane >> 4) & 1) * 8;
    const int brow = (lane & 7) + ((lane >> 4) & 1) * 8;
    const int bcol = ((lane >> 3) & 1) * 8;

    float acc[2][8][4];
    #pragma unroll
    for (int mt = 0; mt < 2; mt++)
        #pragma unroll
        for (int nt = 0; nt < 8; nt++)
            #pragma unroll
            for (int q = 0; q < 4; q++) acc[mt][nt][q] = 0.f;

    float spa_acc[8] = {0,0,0,0,0,0,0,0};
    const float* xcol = x + ((size_t)b * 512 + ty * 4) * 4096 + n0 + tx;

    for (int ci = 0; ci < 8; ci++) {
        const int c0 = ci * 64;
        #pragma unroll
        for (int it = 0; it < 4; it++) {
            int idx = t + it * 256;
            int d = idx >> 3, q = idx & 7;
            int dst = d * TS + q * 16;
            *(uint4*)(smb + WH_B + dst) = *(const uint4*)(g_wh + d * 512 + c0 + q * 8);
            *(uint4*)(smb + WL_B + dst) = *(const uint4*)(g_wl + d * 512 + c0 + q * 8);
        }
        {
            int cc = c0 + ty * 4;
            float s0v[4], b0v[4], s1v[4], b1v[4], swv[4];
            #pragma unroll
            for (int i = 0; i < 4; i++) {
                s0v[i] = s0_s[cc + i]; b0v[i] = b0_s[cc + i];
                s1v[i] = s1_s[cc + i]; b1v[i] = b1_s[cc + i];
                swv[i] = spw_s[cc + i];
            }
            const float* xr = xcol + (size_t)c0 * 4096;
            #pragma unroll
            for (int j = 0; j < 8; j++) {
                int n = tx + 16 * j;
                float yh[4], yl[4];
                #pragma unroll
                for (int i = 0; i < 4; i++) {
                    float xv = xr[(size_t)i * 4096 + 16 * j];
                    float p = lrelu(xv * s0v[i] + b0v[i]);
                    spa_acc[j] += swv[i] * p;
                    float y = lrelu(p * s1v[i] + b1v[i]);
                    float h = __bfloat162float(__float2bfloat16(y));
                    yh[i] = h; yl[i] = y - h;
                }
                unsigned h0 = pack2(yh[0], yh[1]), h1 = pack2(yh[2], yh[3]);
                unsigned l0 = pack2(yl[0], yl[1]), l1 = pack2(yl[2], yl[3]);
                unsigned long long hv = (unsigned long long)h0 | ((unsigned long long)h1 << 32);
                unsigned long long lv = (unsigned long long)l0 | ((unsigned long long)l1 << 32);
                int off = n * TS + ty * 8;
                *(unsigned long long*)(smb + YH_B + off) = hv;
                *(unsigned long long*)(smb + YL_B + off) = lv;
            }
        }
        __syncthreads();

        #pragma unroll
        for (int ks = 0; ks < 4; ks++) {
            const int kb = (ks * 16) * 2;
            uint32_t ah[2][4], al[2][4];
            #pragma unroll
            for (int mt = 0; mt < 2; mt++) {
                uint32_t aoff = (d_base + mt * 16 + arow) * TS + kb + acol * 2;
                LDSM4(ah[mt], smem_u + WH_B + aoff);
                LDSM4(al[mt], smem_u + WL_B + aoff);
            }
            #pragma unroll
            for (int p = 0; p < 4; p++) {
                uint32_t bh[4], bl[4];
                uint32_t boff = (n_base + p * 16 + brow) * TS + kb + bcol * 2;
                LDSM4(bh, smem_u + YH_B + boff);
                LDSM4(bl, smem_u + YL_B + boff);
                #pragma unroll
                for (int mt = 0; mt < 2; mt++) {
                    MMA16816(acc[mt][2*p],   ah[mt], bh[0], bh[1]);
                    MMA16816(acc[mt][2*p+1], ah[mt], bh[2], bh[3]);
                    MMA16816(acc[mt][2*p],   ah[mt], bl[0], bl[1]);
                    MMA16816(acc[mt][2*p+1], ah[mt], bl[2], bl[3]);
                    MMA16816(acc[mt][2*p],   al[mt], bh[0], bh[1]);
                    MMA16816(acc[mt][2*p+1], al[mt], bh[2], bh[3]);
                }
            }
        }
        __syncthreads();
    }

    // spa partials
    #pragma unroll
    for (int j = 0; j < 8; j++) spp[ty * 128 + tx + 16 * j] = spa_acc[j];

    // epilogue: ABN2 -> X_g[b][d][n] (float2 per d-row)
    {
        int dl = lane >> 2;
        int nl = (lane & 3) * 2;
        #pragma unroll
        for (int mt = 0; mt < 2; mt++) {
            int d0 = d_base + mt * 16 + dl;
            float s2a = s2_s[d0],     t2a = t2_s[d0];
            float s2b = s2_s[d0 + 8], t2b = t2_s[d0 + 8];
            float* Xa = g_X + ((size_t)b * 128 + d0) * 4096 + n0;
            float* Xb = g_X + ((size_t)b * 128 + d0 + 8) * 4096 + n0;
            #pragma unroll
            for (int nt = 0; nt < 8; nt++) {
                int nv = n_base + nt * 8 + nl;
                float2 va = make_float2(lrelu(acc[mt][nt][0] * s2a + t2a),
                                        lrelu(acc[mt][nt][1] * s2a + t2a));
                float2 vb = make_float2(lrelu(acc[mt][nt][2] * s2b + t2b),
                                        lrelu(acc[mt][nt][3] * s2b + t2b));
                *(float2*)(Xa + nv) = va;
                *(float2*)(Xb + nv) = vb;
            }
        }
    }
    __syncthreads();

    if (t < 128) {
        float s = 0.f;
        #pragma unroll
        for (int r = 0; r < 16; r++) s += spp[r * 128 + t];
        g_spa[b * 4096 + n0 + t] = sigm(s);
    }
}

// ---------------- K2: k_enc — softmax + partial E over 128-pixel tiles ----------------
// smem floats: X_s[0,16512) stride129 | A_s[16512,18688) stride17 | cwt[18688,20736) [d][k]
//              c2[20736,20752) | sc[20752,20768)
#define SME_BYTES 83072
__global__ void __launch_bounds__(256) k_enc(
    const float* __restrict__ cw, const float* __restrict__ scale)
{
    extern __shared__ float sm[];
    float* X_s  = sm;
    float* A_s  = sm + 16512;
    float* cwt  = sm + 18688;
    float* c2_s = sm + 20736;
    float* sc_s = sm + 20752;

    const int t = threadIdx.x;
    const int b = blockIdx.x >> 5;
    const int tile = blockIdx.x & 31;
    const int n0 = tile * 128;

    // load cw transposed + c2/sc
    for (int i = t; i < 2048; i += 256) {
        int k = i >> 7, d = i & 127;
        cwt[d * 16 + k] = cw[i];
    }
    if (t < 16) {
        float c2 = 0.f;
        for (int d = 0; d < 128; d++) { float v = cw[t * 128 + d]; c2 += v * v; }
        c2_s[t] = c2; sc_s[t] = scale[t];
    }
    // stage X tile: [128 d][128 n] global -> X_s[n][d]
    {
        const float4* Xg = (const float4*)(g_X + (size_t)b * 128 * 4096 + n0);
        for (int idx = t; idx < 4096; idx += 256) {
            int d = idx >> 5, q = idx & 31;
            float4 v = Xg[d * 1024 + q];
            int nb = q * 4;
            X_s[nb * 129 + d]       = v.x;
            X_s[(nb + 1) * 129 + d] = v.y;
            X_s[(nb + 2) * 129 + d] = v.z;
            X_s[(nb + 3) * 129 + d] = v.w;
        }
    }
    __syncthreads();

    // softmax per pixel (t < 128)
    if (t < 128) {
        const float* Xr = X_s + t * 129;
        float dot[16];
        #pragma unroll
        for (int k = 0; k < 16; k++) dot[k] = 0.f;
        float x2 = 0.f;
        for (int d = 0; d < 128; d++) {
            float xv = Xr[d];
            x2 += xv * xv;
            const float4* cr = (const float4*)(cwt + d * 16);
            float4 q0 = cr[0], q1 = cr[1], q2 = cr[2], q3 = cr[3];
            dot[0]  += xv * q0.x; dot[1]  += xv * q0.y; dot[2]  += xv * q0.z; dot[3]  += xv * q0.w;
            dot[4]  += xv * q1.x; dot[5]  += xv * q1.y; dot[6]  += xv * q1.z; dot[7]  += xv * q1.w;
            dot[8]  += xv * q2.x; dot[9]  += xv * q2.y; dot[10] += xv * q2.z; dot[11] += xv * q2.w;
            dot[12] += xv * q3.x; dot[13] += xv * q3.y; dot[14] += xv * q3.z; dot[15] += xv * q3.w;
        }
        float e[16]; float mx = -1e30f;
        #pragma unroll
        for (int k = 0; k < 16; k++) {
            float sl = sc_s[k] * (x2 - 2.f * dot[k] + c2_s[k]);
            e[k] = sl; mx = fmaxf(mx, sl);
        }
        float sum = 0.f;
        #pragma unroll
        for (int k = 0; k < 16; k++) { e[k] = expf(e[k] - mx); sum += e[k]; }
        float inv = 1.f / sum;
        #pragma unroll
        for (int k = 0; k < 16; k++) A_s[t * 17 + k] = e[k] * inv;
    }
    __syncthreads();

    // partial E (K x D) and asum
    {
        int kk = t >> 4;
        int dg = t & 15;
        int d0 = dg * 8;
        float ev[8] = {0,0,0,0,0,0,0,0};
        float as = 0.f;
        for (int n = 0; n < 128; n++) {
            float a = A_s[n * 17 + kk];
            as += a;
            const float* Xr = X_s + n * 129 + d0;
            #pragma unroll
            for (int i = 0; i < 8; i++) ev[i] += a * Xr[i];
        }
        float* pe = g_partE + ((size_t)(b * 32 + tile)) * 2048 + kk * 128 + d0;
        #pragma unroll
        for (int i = 0; i < 8; i++) pe[i] = ev[i];
        if (dg == 0) g_partA[(b * 32 + tile) * 16 + kk] = as;
    }
}

// ---------------- K3: k_redE — per-batch reduce -> enc ----------------
__global__ void __launch_bounds__(256) k_redE(
    const float* __restrict__ cw, float* __restrict__ out_enc)
{
    __shared__ float asum_s[16];
    __shared__ float red[256];
    const int b = blockIdx.x, t = threadIdx.x;
    const int base = t * 8;

    float ef[8] = {0,0,0,0,0,0,0,0};
    for (int tl = 0; tl < 32; tl++) {
        const float4* p = (const float4*)(g_partE + ((size_t)(b * 32 + tl)) * 2048 + base);
        float4 u0 = p[0], u1 = p[1];
        ef[0]+=u0.x; ef[1]+=u0.y; ef[2]+=u0.z; ef[3]+=u0.w;
        ef[4]+=u1.x; ef[5]+=u1.y; ef[6]+=u1.z; ef[7]+=u1.w;
    }
    if (t < 16) {
        float s = 0.f;
        for (int tl = 0; tl < 32; tl++) s += g_partA[(b * 32 + tl) * 16 + t];
        asum_s[t] = s;
    }
    __syncthreads();

    int k = base >> 7;
    float a = asum_s[k];
    float fin[8]; float ss = 0.f;
    #pragma unroll
    for (int i = 0; i < 8; i++) {
        fin[i] = ef[i] - a * cw[base + i];
        ss += fin[i] * fin[i];
    }
    red[t] = ss; __syncthreads();
    for (int s = 128; s > 0; s >>= 1) {
        if (t < s) red[t] += red[t + s];
        __syncthreads();
    }
    float inv = 1.f / fmaxf(sqrtf(red[0]), 1e-12f);
    #pragma unroll
    for (int i = 0; i < 8; i++) {
        float e = fin[i] * inv;
        g_enc[b * 2048 + base + i] = e;
        out_enc[b * 2048 + base + i] = e;
    }
}

// ---------------- K4: k_se — channel SE matvec (128 blocks) ----------------
__global__ void __launch_bounds__(256) k_se(
    const float* __restrict__ se_w, const float* __restrict__ se_b)
{
    __shared__ float enc_s[2048];
    const int t = threadIdx.x;
    const int b = blockIdx.x >> 3;
    const int cg = blockIdx.x & 7;

    for (int i = t; i < 512; i += 256)
        ((float4*)enc_s)[i] = ((const float4*)(g_enc + b * 2048))[i];
    __syncthreads();

    int cl = t >> 2, part = t & 3;
    int c = cg * 64 + cl;
    const float4* wr = (const float4*)(se_w + (size_t)c * 2048) + part * 128;
    const float4* er = (const float4*)enc_s + part * 128;
    float dot = 0.f;
    #pragma unroll 4
    for (int j = 0; j < 128; j++) {
        float4 w4 = wr[j], e4 = er[j];
        dot += w4.x*e4.x + w4.y*e4.y + w4.z*e4.z + w4.w*e4.w;
    }
    dot += __shfl_xor_sync(0xFFFFFFFF, dot, 1);
    dot += __shfl_xor_sync(0xFFFFFFFF, dot, 2);
    if (part == 0) g_chn[b * 512 + c] = sigm(dot + se_b[c]);
}

// ---------------- K5: out = x * spa_se * chn_se ----------------
__global__ void __launch_bounds__(256) k_out(const float* __restrict__ x, float* __restrict__ out) {
    size_t i = (size_t)blockIdx.x * 256 + threadIdx.x;
    int bi = (int)(i >> 19);
    size_t r = i & 524287;
    int c = (int)(r >> 10);
    int n4 = (int)(r & 1023);
    float4 xv = ((const float4*)x)[i];
    float4 sp = ((const float4*)g_spa)[(size_t)bi * 1024 + n4];
    float ch = g_chn[bi * 512 + c];
    float4 o;
    o.x = xv.x * sp.x * ch;
    o.y = xv.y * sp.y * ch;
    o.z = xv.z * sp.z * ch;
    o.w = xv.w * sp.w * ch;
    ((float4*)out)[i] = o;
}

// ---------------- launch ----------------
extern "C" void kernel_launch(void* const* d_in, const int* in_sizes, int n_in,
                              void* d_out, int out_size) {
    const float* x      = (const float*)d_in[0];
    const float* pre_g  = (const float*)d_in[1];
    const float* pre_b  = (const float*)d_in[2];
    const float* pre_m  = (const float*)d_in[3];
    const float* pre_v  = (const float*)d_in[4];
    const float* a1_g   = (const float*)d_in[5];
    const float* a1_b   = (const float*)d_in[6];
    const float* a1_m   = (const float*)d_in[7];
    const float* a1_v   = (const float*)d_in[8];
    const float* conv_w = (const float*)d_in[9];
    const float* conv_b = (const float*)d_in[10];
    const float* a2_g   = (const float*)d_in[11];
    const float* a2_b   = (const float*)d_in[12];
    const float* a2_m   = (const float*)d_in[13];
    const float* a2_v   = (const float*)d_in[14];
    const float* cw     = (const float*)d_in[15];
    const float* scale  = (const float*)d_in[16];
    const float* se_w   = (const float*)d_in[17];
    const float* se_b   = (const float*)d_in[18];
    const float* spa_w  = (const float*)d_in[19];
    float* out = (float*)d_out;

    cudaFuncSetAttribute(k_gemm, cudaFuncAttributeMaxDynamicSharedMemorySize, SMG_BYTES);
    cudaFuncSetAttribute(k_enc,  cudaFuncAttributeMaxDynamicSharedMemorySize, SME_BYTES);

    k_split_w<<<256, 256>>>(conv_w);
    k_gemm<<<512, 256, SMG_BYTES>>>(x, pre_g, pre_b, pre_m, pre_v,
                                    a1_g, a1_b, a1_m, a1_v,
                                    conv_b, a2_g, a2_b, a2_m, a2_v, spa_w);
    k_enc<<<512, 256, SME_BYTES>>>(cw, scale);
    k_redE<<<16, 256>>>(cw, out);
    k_se<<<128, 256>>>(se_w, se_b);
    k_out<<<32768, 256>>>(x, out + 32768);
}